// round 17
// baseline (speedup 1.0000x reference)
#include <cuda_runtime.h>
#include <cuda_bf16.h>
#include <cstdint>

#define N_NODES 50000
#define N_EDGES 800000

#define M_TILE   64
#define THREADS  128
#define N_TILES  ((N_NODES + M_TILE - 1) / M_TILE)   // 782
#define GRID     592                                  // 148 SM x 4 CTA, all resident
#define STRIDE   (GRID * THREADS)                     // 75776

// ---------------------------------------------------------------------------
// Device scratch. g_flag zero at load; each tile's flags re-zeroed after use
// every run (graph-replay invariant). g_Wfrag rebuilt deterministically each
// run. g_bar is a monotonically increasing ticket barrier (generation-based,
// replay-safe).
// ---------------------------------------------------------------------------
__device__ int g_flag[N_NODES];
__device__ __align__(16) uint4 g_Wfrag[8 * 16 * 32];      // 64 KB
__device__ unsigned long long g_bar;

// ---------------------------------------------------------------------------
// Blocked SW128 atom layout for a [64 x 128] bf16 tile (A staging).
// ---------------------------------------------------------------------------
__host__ __device__ __forceinline__ uint32_t tile_off(int r, int k) {
    uint32_t off = ((uint32_t)((r >> 3) + ((k >> 6) << 3))) * 1024u
                 + (uint32_t)(r & 7) * 128u + (uint32_t)(k & 63) * 2u;
    return off ^ ((off >> 3) & 0x70);
}

__device__ __forceinline__ uint32_t smem_u32(const void* p) {
    uint32_t a;
    asm("{ .reg .u64 t; cvta.to.shared.u64 t, %1; cvt.u32.u64 %0, t; }" : "=r"(a) : "l"(p));
    return a;
}

__device__ __forceinline__ void mma16816(float* d, const uint32_t* a, uint32_t b0, uint32_t b1) {
    asm volatile(
        "mma.sync.aligned.m16n8k16.row.col.f32.bf16.bf16.f32 "
        "{%0,%1,%2,%3}, {%4,%5,%6,%7}, {%8,%9}, {%0,%1,%2,%3};"
        : "+f"(d[0]), "+f"(d[1]), "+f"(d[2]), "+f"(d[3])
        : "r"(a[0]), "r"(a[1]), "r"(a[2]), "r"(a[3]), "r"(b0), "r"(b1));
}

__device__ __forceinline__ void ldmx4(uint32_t* r, uint32_t addr) {
    asm volatile("ldmatrix.sync.aligned.m8n8.x4.shared.b16 {%0,%1,%2,%3}, [%4];"
                 : "=r"(r[0]), "=r"(r[1]), "=r"(r[2]), "=r"(r[3]) : "r"(addr));
}

__device__ __forceinline__ void split2(float2 v, uint32_t& hi, uint32_t& lo) {
    __nv_bfloat162 h, l;
    h.x = __float2bfloat16(v.x);
    h.y = __float2bfloat16(v.y);
    l.x = __float2bfloat16(v.x - __bfloat162float(h.x));
    l.y = __float2bfloat16(v.y - __bfloat162float(h.y));
    hi = *(uint32_t*)&h;
    lo = *(uint32_t*)&l;
}

__device__ __forceinline__ float2 bf2sum(uint32_t h, uint32_t l) {
    __nv_bfloat162 hb = *(__nv_bfloat162*)&h;
    __nv_bfloat162 lb = *(__nv_bfloat162*)&l;
    return make_float2(__bfloat162float(hb.x) + __bfloat162float(lb.x),
                       __bfloat162float(hb.y) + __bfloat162float(lb.y));
}

// ---------------------------------------------------------------------------
// Single persistent kernel:
//  phase 1: build W fragments + mark dst flags (strided over all CTAs)
//  phase 2: pre-stage this CTA's first x tile (independent of phase 1 data)
//  phase 3: device-wide ticket barrier
//  phase 4: loop tiles: mainloop (mma) + fused LayerNorm epilogue
// ---------------------------------------------------------------------------
#define SM_XHI 0
#define SM_XLO 16384
#define SM_DYN 32768
#define MARK_CHUNK (N_EDGES / 4)

__global__ __launch_bounds__(THREADS, 4) void fused_all_kernel(
    const float* __restrict__ x,
    const int*   __restrict__ edge_index,
    const float* __restrict__ Wv,
    const float* __restrict__ gamma,
    const float* __restrict__ beta,
    float* __restrict__ out)
{
    extern __shared__ char smem[];
    __shared__ float sg[128], sb[128];
    __shared__ float psum[M_TILE * 2], psq[M_TILE * 2];

    const uint32_t sbase = smem_u32(smem);
    const int tid  = threadIdx.x;
    const int w    = tid >> 5;
    const int lane = tid & 31;
    const int rw   = w >> 1;           // row group 0..1 (32 rows each)
    const int ch   = w & 1;            // column half
    const int gthr = blockIdx.x * THREADS + tid;

    // ---- phase 1a: W fragment build (4096 entries; one per low gthr) ------
    if (gthr < 8 * 16 * 32) {
        int idx  = gthr;                          // (kt*16+nt)*32+lane
        int ln   = idx & 31;
        int nt   = (idx >> 5) & 15;
        int kt   = idx >> 9;
        int n  = 8 * nt + (ln >> 2);
        int k0 = 16 * kt + 2 * (ln & 3);

        float w00 = Wv[(size_t)k0 * 128 + n];
        float w01 = Wv[(size_t)(k0 + 1) * 128 + n];
        float w10 = Wv[(size_t)(k0 + 8) * 128 + n];
        float w11 = Wv[(size_t)(k0 + 9) * 128 + n];

        uint32_t h0, l0, h1, l1;
        split2(make_float2(w00, w01), h0, l0);
        split2(make_float2(w10, w11), h1, l1);
        g_Wfrag[idx] = make_uint4(h0, h1, l0, l1);
    }

    // ---- phase 1b: edge-dst marking (int4-vectorized, strided) ------------
    for (int i = gthr; i < MARK_CHUNK; i += STRIDE) {
        int4 d = ((const int4*)(edge_index + N_EDGES))[i];
        if ((unsigned)d.x < N_NODES) g_flag[d.x] = 1;
        if ((unsigned)d.y < N_NODES) g_flag[d.y] = 1;
        if ((unsigned)d.z < N_NODES) g_flag[d.z] = 1;
        if ((unsigned)d.w < N_NODES) g_flag[d.w] = 1;
    }
    __threadfence();   // make this thread's flag/Wfrag stores device-visible

    sg[tid] = gamma[tid];
    sb[tid] = beta[tid];

    // ---- phase 2: pre-stage first tile (hides behind barrier wait) --------
    {
        const int row0 = blockIdx.x * M_TILE;
#pragma unroll
        for (int i = 0; i < 16; i++) {
            int idx4 = tid + i * 128;
            int r  = idx4 >> 5;
            int c4 = idx4 & 31;
            int rr = min(row0 + r, N_NODES - 1);
            float4 v = ((const float4*)x)[(size_t)rr * 32 + c4];
            uint32_t h01, l01, h23, l23;
            split2(make_float2(v.x, v.y), h01, l01);
            split2(make_float2(v.z, v.w), h23, l23);
            uint32_t off = tile_off(r, c4 << 2);
            *(uint2*)(smem + SM_XHI + off) = make_uint2(h01, h23);
            *(uint2*)(smem + SM_XLO + off) = make_uint2(l01, l23);
        }
    }
    __syncthreads();   // all CTA threads finished marking + staging

    // ---- phase 3: device-wide ticket barrier (generation-based) -----------
    if (tid == 0) {
        unsigned long long ticket = atomicAdd(&g_bar, 1ULL);
        unsigned long long target = (ticket / (unsigned long long)GRID + 1ULL)
                                    * (unsigned long long)GRID;
        unsigned long long v;
        do {
            asm volatile("ld.volatile.global.u64 %0, [%1];" : "=l"(v) : "l"(&g_bar));
        } while (v < target);
        __threadfence();
    }
    __syncthreads();

    // ---- A-side ldmatrix address precompute (tile-independent) ------------
    const int selA  = lane >> 3;
    const int laneR = (lane & 7) + ((selA & 1) << 3);
    const int kOffA = (selA & 2) << 2;

    const int rA0 = 32 * rw + laneR;
    const int rA1 = rA0 + 16;
    const uint32_t rb0 = (uint32_t)(rA0 >> 3) * 1024u + (uint32_t)(rA0 & 7) * 128u;
    const uint32_t rb1 = (uint32_t)(rA1 >> 3) * 1024u + (uint32_t)(rA1 & 7) * 128u;
    const uint32_t xo0 = (uint32_t)(rA0 & 7) << 4;
    const uint32_t xo1 = (uint32_t)(rA1 & 7) << 4;

    const uint4* fragp = g_Wfrag + (8 * ch) * 32 + lane;

    const int g = lane >> 2;
    const int t = lane & 3;
    const uint32_t cxor = (uint32_t)(4 * t);

    // ---- phase 4: tile loop ----------------------------------------------
    for (int tile = blockIdx.x; tile < N_TILES; tile += GRID) {
        const int row0 = tile * M_TILE;

        if (tile != blockIdx.x) {
            // stage this tile (first tile was pre-staged)
#pragma unroll
            for (int i = 0; i < 16; i++) {
                int idx4 = tid + i * 128;
                int r  = idx4 >> 5;
                int c4 = idx4 & 31;
                int rr = min(row0 + r, N_NODES - 1);
                float4 v = ((const float4*)x)[(size_t)rr * 32 + c4];
                uint32_t h01, l01, h23, l23;
                split2(make_float2(v.x, v.y), h01, l01);
                split2(make_float2(v.z, v.w), h23, l23);
                uint32_t off = tile_off(r, c4 << 2);
                *(uint2*)(smem + SM_XHI + off) = make_uint2(h01, h23);
                *(uint2*)(smem + SM_XLO + off) = make_uint2(l01, l23);
            }
            __syncthreads();
        }

        float acc[2][8][4];
#pragma unroll
        for (int mt = 0; mt < 2; mt++)
#pragma unroll
            for (int nt = 0; nt < 8; nt++)
#pragma unroll
                for (int i = 0; i < 4; i++) acc[mt][nt][i] = 0.0f;

#pragma unroll
        for (int kt = 0; kt < 8; kt++) {
            const int kk = 16 * kt + kOffA;
            const uint32_t katom = (uint32_t)((kk >> 6) << 13);
            const uint32_t klow  = (uint32_t)((kk & 63) * 2);
            const uint32_t o0 = rb0 + katom + (klow ^ xo0);
            const uint32_t o1 = rb1 + katom + (klow ^ xo1);

            uint32_t ah0[4], al0[4], ah1[4], al1[4];
            ldmx4(ah0, sbase + SM_XHI + o0);
            ldmx4(al0, sbase + SM_XLO + o0);
            ldmx4(ah1, sbase + SM_XHI + o1);
            ldmx4(al1, sbase + SM_XLO + o1);

            const uint4* fk = fragp + kt * 512;
#pragma unroll
            for (int h = 0; h < 2; h++) {
                uint4 f0 = __ldg(fk + (4 * h + 0) * 32);
                uint4 f1 = __ldg(fk + (4 * h + 1) * 32);
                uint4 f2 = __ldg(fk + (4 * h + 2) * 32);
                uint4 f3 = __ldg(fk + (4 * h + 3) * 32);
                const int n0 = 4 * h;

                // product-major passes: acc touched at issue distance 8
                mma16816(acc[0][n0 + 0], ah0, f0.x, f0.y);
                mma16816(acc[0][n0 + 1], ah0, f1.x, f1.y);
                mma16816(acc[0][n0 + 2], ah0, f2.x, f2.y);
                mma16816(acc[0][n0 + 3], ah0, f3.x, f3.y);
                mma16816(acc[1][n0 + 0], ah1, f0.x, f0.y);
                mma16816(acc[1][n0 + 1], ah1, f1.x, f1.y);
                mma16816(acc[1][n0 + 2], ah1, f2.x, f2.y);
                mma16816(acc[1][n0 + 3], ah1, f3.x, f3.y);

                mma16816(acc[0][n0 + 0], ah0, f0.z, f0.w);
                mma16816(acc[0][n0 + 1], ah0, f1.z, f1.w);
                mma16816(acc[0][n0 + 2], ah0, f2.z, f2.w);
                mma16816(acc[0][n0 + 3], ah0, f3.z, f3.w);
                mma16816(acc[1][n0 + 0], ah1, f0.z, f0.w);
                mma16816(acc[1][n0 + 1], ah1, f1.z, f1.w);
                mma16816(acc[1][n0 + 2], ah1, f2.z, f2.w);
                mma16816(acc[1][n0 + 3], ah1, f3.z, f3.w);

                mma16816(acc[0][n0 + 0], al0, f0.x, f0.y);
                mma16816(acc[0][n0 + 1], al0, f1.x, f1.y);
                mma16816(acc[0][n0 + 2], al0, f2.x, f2.y);
                mma16816(acc[0][n0 + 3], al0, f3.x, f3.y);
                mma16816(acc[1][n0 + 0], al1, f0.x, f0.y);
                mma16816(acc[1][n0 + 1], al1, f1.x, f1.y);
                mma16816(acc[1][n0 + 2], al1, f2.x, f2.y);
                mma16816(acc[1][n0 + 3], al1, f3.x, f3.y);
            }
        }

        // ---- epilogue: h = x + V*flag, single-pass LN stats ---------------
#pragma unroll
        for (int mt = 0; mt < 2; mt++) {
            const int r0 = 32 * rw + 16 * mt + g;
            const int r1 = r0 + 8;
            const int rc0 = min(row0 + r0, N_NODES - 1);
            const int rc1 = min(row0 + r1, N_NODES - 1);
            const float fac0 = (float)g_flag[rc0];
            const float fac1 = (float)g_flag[rc1];

            const uint32_t rbe0 = (uint32_t)(r0 >> 3) * 1024u + (uint32_t)(r0 & 7) * 128u
                                + ((uint32_t)ch << 13);
            const uint32_t rbe1 = (uint32_t)(r1 >> 3) * 1024u + (uint32_t)(r1 & 7) * 128u
                                + ((uint32_t)ch << 13);
            const uint32_t xe0 = (uint32_t)(r0 & 7) << 4;
            const uint32_t xe1 = (uint32_t)(r1 & 7) << 4;

            float s0 = 0.0f, s1 = 0.0f, q0 = 0.0f, q1 = 0.0f;
#pragma unroll
            for (int nt = 0; nt < 8; nt++) {
                const uint32_t cl = (uint32_t)(16 * nt) + cxor;
                const uint32_t off0 = rbe0 + (cl ^ xe0);
                const uint32_t off1 = rbe1 + (cl ^ xe1);
                uint32_t xh0 = *(const uint32_t*)(smem + SM_XHI + off0);
                uint32_t xl0 = *(const uint32_t*)(smem + SM_XLO + off0);
                uint32_t xh1 = *(const uint32_t*)(smem + SM_XHI + off1);
                uint32_t xl1 = *(const uint32_t*)(smem + SM_XLO + off1);
                float2 x0 = bf2sum(xh0, xl0);
                float2 x1 = bf2sum(xh1, xl1);

                float h00 = fmaf(acc[mt][nt][0], fac0, x0.x);
                float h01 = fmaf(acc[mt][nt][1], fac0, x0.y);
                float h10 = fmaf(acc[mt][nt][2], fac1, x1.x);
                float h11 = fmaf(acc[mt][nt][3], fac1, x1.y);
                acc[mt][nt][0] = h00; acc[mt][nt][1] = h01;
                acc[mt][nt][2] = h10; acc[mt][nt][3] = h11;
                s0 += h00 + h01;
                s1 += h10 + h11;
                q0 = fmaf(h00, h00, fmaf(h01, h01, q0));
                q1 = fmaf(h10, h10, fmaf(h11, h11, q1));
            }
            s0 += __shfl_xor_sync(0xffffffffu, s0, 1);
            s0 += __shfl_xor_sync(0xffffffffu, s0, 2);
            s1 += __shfl_xor_sync(0xffffffffu, s1, 1);
            s1 += __shfl_xor_sync(0xffffffffu, s1, 2);
            q0 += __shfl_xor_sync(0xffffffffu, q0, 1);
            q0 += __shfl_xor_sync(0xffffffffu, q0, 2);
            q1 += __shfl_xor_sync(0xffffffffu, q1, 1);
            q1 += __shfl_xor_sync(0xffffffffu, q1, 2);
            if (t == 0) {
                psum[r0 * 2 + ch] = s0; psum[r1 * 2 + ch] = s1;
                psq[r0 * 2 + ch]  = q0; psq[r1 * 2 + ch]  = q1;
            }
        }
        __syncthreads();

        // re-zero this tile's flags for next graph replay (facs already read)
        if (tid < M_TILE) {
            int rz = row0 + tid;
            if (rz < N_NODES) g_flag[rz] = 0;
        }

#pragma unroll
        for (int mt = 0; mt < 2; mt++) {
            const int r0 = 32 * rw + 16 * mt + g;
            const int r1 = r0 + 8;
            const float mu0 = (psum[r0 * 2] + psum[r0 * 2 + 1]) * (1.0f / 128.0f);
            const float mu1 = (psum[r1 * 2] + psum[r1 * 2 + 1]) * (1.0f / 128.0f);
            const float var0 = fmaf(-mu0, mu0, (psq[r0 * 2] + psq[r0 * 2 + 1]) * (1.0f / 128.0f));
            const float var1 = fmaf(-mu1, mu1, (psq[r1 * 2] + psq[r1 * 2 + 1]) * (1.0f / 128.0f));
            const float inv0 = rsqrtf(var0 + 1e-5f);
            const float inv1 = rsqrtf(var1 + 1e-5f);

            const int row0g = row0 + r0;
            const int row1g = row0 + r1;

#pragma unroll
            for (int nt = 0; nt < 8; nt++) {
                const int c = 64 * ch + 8 * nt + 2 * t;
                float2 gm = *(const float2*)(sg + c);
                float2 bt = *(const float2*)(sb + c);
                if (row0g < N_NODES) {
                    float2 o;
                    o.x = fmaf((acc[mt][nt][0] - mu0) * inv0, gm.x, bt.x);
                    o.y = fmaf((acc[mt][nt][1] - mu0) * inv0, gm.y, bt.y);
                    *(float2*)(out + (size_t)row0g * 128 + c) = o;
                }
                if (row1g < N_NODES) {
                    float2 o;
                    o.x = fmaf((acc[mt][nt][2] - mu1) * inv1, gm.x, bt.x);
                    o.y = fmaf((acc[mt][nt][3] - mu1) * inv1, gm.y, bt.y);
                    *(float2*)(out + (size_t)row1g * 128 + c) = o;
                }
            }
        }
        __syncthreads();   // protect smem tile before next iteration's staging
    }
}

// ---------------------------------------------------------------------------
extern "C" void kernel_launch(void* const* d_in, const int* in_sizes, int n_in,
                              void* d_out, int out_size)
{
    const float* x          = (const float*)d_in[0];
    const int*   edge_index = (const int*)d_in[1];
    const float* Wv         = (const float*)d_in[5];
    const float* gamma      = (const float*)d_in[7];
    const float* beta       = (const float*)d_in[8];
    float*       out        = (float*)d_out;

    cudaFuncSetAttribute(fused_all_kernel,
                         cudaFuncAttributeMaxDynamicSharedMemorySize, SM_DYN);

    fused_all_kernel<<<GRID, THREADS, SM_DYN>>>(x, edge_index, Wv, gamma, beta, out);
}